// round 6
// baseline (speedup 1.0000x reference)
#include <cuda_runtime.h>

typedef unsigned long long u64;

#define N_AGENTS 4096
#define TOPK 12
#define SEL 16
#define EPSC 1e-4f
#define TWPB 8                         // warps (rows) per topk block
#define BUFD 6
#define TOPK_BLOCKS (N_AGENTS / TWPB)  // 512

__device__ float2 g_W1p[6 * 32];        // [i][lane] -> w1 for outputs lane+{0,32}
__device__ float2 g_W2p[64 * 2 * 32];   // [i][pass][lane] -> w2 for o = lane+64p+{0,32}
__device__ float2 g_W3p[128 * 32];      // [i][lane] -> w3 for outputs lane+{0,32}
__device__ float2 g_xy[N_AGENTS];       // packed (x,y)
__device__ int    g_idx[N_AGENTS * TOPK];
__device__ float  g_dn [N_AGENTS * TOPK];

static __device__ __forceinline__ u64 umin64(u64 a, u64 b) { return a < b ? a : b; }
static __device__ __forceinline__ u64 pack2(float w) {
    u64 r; asm("mov.b64 %0, {%1, %1};" : "=l"(r) : "f"(w)); return r;
}
static __device__ __forceinline__ void ffma2(u64 &d, u64 a, u64 b) {
    asm("fma.rn.f32x2 %0, %1, %2, %0;" : "+l"(d) : "l"(a), "l"(b));
}
static __device__ __forceinline__ float2 unpack2(u64 v) {
    return make_float2(__uint_as_float((unsigned)v), __uint_as_float((unsigned)(v >> 32)));
}

// ============================ pack kernel ============================
__global__ void pack_kernel(const float* __restrict__ states,
                            const float* __restrict__ W1,
                            const float* __restrict__ W2,
                            const float* __restrict__ W3)
{
    int t = blockIdx.x * blockDim.x + threadIdx.x;   // 0..8191
    float* w1p = (float*)g_W1p;
    float* w2p = (float*)g_W2p;
    float* w3p = (float*)g_W3p;
    if (t < 8192) {
        { // W2p: [i][p][lane] float2
            int idx2 = t >> 1, comp = t & 1;
            int i = idx2 >> 6, rem = idx2 & 63, p = rem >> 5, lane = rem & 31;
            int o = lane + 64 * p + 32 * comp;
            w2p[t] = W2[o * 64 + i];
        }
        { // W3p
            int idx2 = t >> 1, comp = t & 1;
            int i = idx2 >> 5, lane = idx2 & 31;
            int o = lane + 32 * comp;
            w3p[t] = W3[o * 128 + i];
        }
        if (t < 384) { // W1p
            int idx2 = t >> 1, comp = t & 1;
            int i = idx2 >> 5, lane = idx2 & 31;
            int o = lane + 32 * comp;
            w1p[t] = W1[o * 6 + i];
        }
        if (t < N_AGENTS)
            g_xy[t] = make_float2(states[t * 4], states[t * 4 + 1]);
    }
}

// ============================ exact top-k ============================
static __device__ __forceinline__ void warp_merge(
    u64 &topent, u64 &thrkey, int &bcnt, u64 (*buf)[32], int lane)
{
    u64 v[BUFD];
#pragma unroll
    for (int s = 0; s < BUFD; s++) v[s] = (s < bcnt) ? buf[s][lane] : ~0ULL;
    u64 oldtop = topent;
    u64 newtop = ~0ULL;
#pragma unroll 1
    for (int r = 0; r < SEL; r++) {
        u64 lm = oldtop;
#pragma unroll
        for (int s = 0; s < BUFD; s++) lm = umin64(lm, v[s]);
#pragma unroll
        for (int o = 16; o > 0; o >>= 1)
            lm = umin64(lm, __shfl_xor_sync(0xffffffffu, lm, o));
        if (oldtop == lm) oldtop = ~0ULL;
#pragma unroll
        for (int s = 0; s < BUFD; s++) if (v[s] == lm) v[s] = ~0ULL;
        if (lane == r) newtop = lm;
        thrkey = lm;
    }
    topent = newtop;
    bcnt = 0;
}

__global__ __launch_bounds__(32 * TWPB) void topk_kernel()
{
    __shared__ u64 sbuf[TWPB][BUFD][32];

    const int warp = threadIdx.x >> 5;
    const int lane = threadIdx.x & 31;
    const int row  = blockIdx.x * TWPB + warp;
    const float2 sr = g_xy[row];
    const float xi = sr.x, yi = sr.y;
    const float4* xy4 = reinterpret_cast<const float4*>(g_xy);

    u64 topent = ~0ULL, thrkey = ~0ULL;
    int bcnt = 0;

#pragma unroll 1
    for (int m = 0; m < N_AGENTS / 64; m++) {
        float4 p = xy4[m * 32 + lane];         // candidates j0, j0+1
        int j0 = m * 64 + 2 * lane;
        float dx0 = __fsub_rn(xi, p.x);
        float dy0 = __fsub_rn(yi, p.y);
        float d20 = __fadd_rn(__fadd_rn(__fmul_rn(dx0, dx0), EPSC),
                              __fadd_rn(__fmul_rn(dy0, dy0), EPSC));
        float dx1 = __fsub_rn(xi, p.z);
        float dy1 = __fsub_rn(yi, p.w);
        float d21 = __fadd_rn(__fadd_rn(__fmul_rn(dx1, dx1), EPSC),
                              __fadd_rn(__fmul_rn(dy1, dy1), EPSC));
        u64 key0 = ((u64)__float_as_uint(d20) << 32) | (unsigned)j0;
        u64 key1 = ((u64)__float_as_uint(d21) << 32) | (unsigned)(j0 + 1);
        if (key0 < thrkey) { sbuf[warp][bcnt][lane] = key0; bcnt++; }
        if (key1 < thrkey) { sbuf[warp][bcnt][lane] = key1; bcnt++; }
        if (__ballot_sync(0xffffffffu, bcnt > BUFD - 2))
            warp_merge(topent, thrkey, bcnt, sbuf[warp], lane);
    }
    if (__ballot_sync(0xffffffffu, bcnt > 0))
        warp_merge(topent, thrkey, bcnt, sbuf[warp], lane);

    // re-rank survivors by (dn, idx) — JAX top_k tie semantics
    float d2v = __uint_as_float((unsigned)(topent >> 32));
    int   jv  = (int)(unsigned)(topent & 0xffffffffu);
    float dnv = __fsqrt_rn(d2v);
    int rank = 0;
#pragma unroll
    for (int ml = 0; ml < SEL; ml++) {
        float dm = __shfl_sync(0xffffffffu, dnv, ml);
        int   jm = __shfl_sync(0xffffffffu, jv,  ml);
        if (ml != lane && (dm < dnv || (dm == dnv && jm < jv))) rank++;
    }
    if (lane < SEL && rank < TOPK) {
        g_idx[row * TOPK + rank] = jv;
        g_dn [row * TOPK + rank] = dnv;
    }
}

// ============================ MLP: warp per agent, 2 out/lane ============================
__global__ __launch_bounds__(128, 8) void mlp_kernel(
    const float4* __restrict__ states,
    const float* __restrict__ b1, const float* __restrict__ b2,
    const float* __restrict__ b3,
    const float* __restrict__ W4, const float* __restrict__ b4,
    float* __restrict__ out, int out_size)
{
    __shared__ alignas(16) float xflat_s[4][80];    // [12 kk][6 cc] (+pad)
    __shared__ alignas(16) float zA_s[4][768];      // z1 [64][12]; reused as z3t [12][64]
    __shared__ alignas(16) float zB_s[4][1536];     // z2 [128][12]

    const int t = threadIdx.x;
    const int w = t >> 5;
    const int lane = t & 31;
    const int a = blockIdx.x * 4 + w;

    float* xflat = xflat_s[w];
    float* zA = zA_s[w];
    float* zB = zB_s[w];

    float maskr = 0.0f;
    if (lane < TOPK) {
        int   idx = g_idx[a * TOPK + lane];
        float dn  = g_dn [a * TOPK + lane];
        float4 si = states[a];
        float4 sj = states[idx];
        xflat[lane * 6 + 0] = __fsub_rn(si.x, sj.x);
        xflat[lane * 6 + 1] = __fsub_rn(si.y, sj.y);
        xflat[lane * 6 + 2] = __fsub_rn(si.z, sj.z);
        xflat[lane * 6 + 3] = __fsub_rn(si.w, sj.w);
        xflat[lane * 6 + 4] = (idx == a) ? 1.0f : 0.0f;
        xflat[lane * 6 + 5] = __fsub_rn(dn, 0.8f);
        maskr = (dn <= 1.0f) ? 1.0f : 0.0f;
    }
    __syncwarp();

    // ---- layer 1: 6 -> 64, 2 outputs/lane ----
    {
        u64 acc[12];
        u64 bb0 = pack2(b1[lane]), bb1 = pack2(b1[lane + 32]);
#pragma unroll
        for (int p = 0; p < 6; p++) { acc[p] = bb0; acc[6 + p] = bb1; }
        const u64* xu = reinterpret_cast<const u64*>(xflat);
#pragma unroll
        for (int i = 0; i < 6; i++) {
            float2 wv = g_W1p[i * 32 + lane];
            u64 w0 = pack2(wv.x), w1 = pack2(wv.y);
#pragma unroll
            for (int p = 0; p < 6; p++) {
                u64 xp = xu[i * 6 + p];
                ffma2(acc[p], w0, xp);
                ffma2(acc[6 + p], w1, xp);
            }
        }
        float2* zA2 = reinterpret_cast<float2*>(zA);
#pragma unroll
        for (int p = 0; p < 6; p++) {
            float2 u = unpack2(acc[p]);
            zA2[lane * 6 + p] = make_float2(fmaxf(u.x, 0.f), fmaxf(u.y, 0.f));
            float2 v = unpack2(acc[6 + p]);
            zA2[(lane + 32) * 6 + p] = make_float2(fmaxf(v.x, 0.f), fmaxf(v.y, 0.f));
        }
    }
    __syncwarp();

    // ---- layer 2: 64 -> 128, two passes of 2 outputs/lane (o = lane+64p+{0,32}) ----
    float2* zB2 = reinterpret_cast<float2*>(zB);
    const ulonglong2* zv1 = reinterpret_cast<const ulonglong2*>(zA);
#pragma unroll 1
    for (int p = 0; p < 2; p++) {
        u64 acc[12];
        u64 bb0 = pack2(b2[lane + 64 * p]), bb1 = pack2(b2[lane + 64 * p + 32]);
#pragma unroll
        for (int q = 0; q < 6; q++) { acc[q] = bb0; acc[6 + q] = bb1; }
#pragma unroll 2
        for (int i = 0; i < 64; i++) {
            float2 wv = g_W2p[(i * 2 + p) * 32 + lane];
            u64 w0 = pack2(wv.x), w1 = pack2(wv.y);
            ulonglong2 p0 = zv1[i * 3 + 0];
            ulonglong2 p1 = zv1[i * 3 + 1];
            ulonglong2 p2 = zv1[i * 3 + 2];
            ffma2(acc[0],  w0, p0.x); ffma2(acc[1],  w0, p0.y);
            ffma2(acc[2],  w0, p1.x); ffma2(acc[3],  w0, p1.y);
            ffma2(acc[4],  w0, p2.x); ffma2(acc[5],  w0, p2.y);
            ffma2(acc[6],  w1, p0.x); ffma2(acc[7],  w1, p0.y);
            ffma2(acc[8],  w1, p1.x); ffma2(acc[9],  w1, p1.y);
            ffma2(acc[10], w1, p2.x); ffma2(acc[11], w1, p2.y);
        }
#pragma unroll
        for (int q = 0; q < 6; q++) {
            float2 u = unpack2(acc[q]);
            zB2[(lane + 64 * p) * 6 + q] = make_float2(fmaxf(u.x, 0.f), fmaxf(u.y, 0.f));
            float2 v = unpack2(acc[6 + q]);
            zB2[(lane + 64 * p + 32) * 6 + q] = make_float2(fmaxf(v.x, 0.f), fmaxf(v.y, 0.f));
        }
    }
    __syncwarp();

    // ---- layer 3: 128 -> 64, 2 outputs/lane; store transposed z3t[L][64] ----
    float* z3t = zA;   // reuse
    {
        u64 acc[12];
        u64 bb0 = pack2(b3[lane]), bb1 = pack2(b3[lane + 32]);
#pragma unroll
        for (int p = 0; p < 6; p++) { acc[p] = bb0; acc[6 + p] = bb1; }
        const ulonglong2* zv = reinterpret_cast<const ulonglong2*>(zB);
#pragma unroll 2
        for (int i = 0; i < 128; i++) {
            float2 wv = g_W3p[i * 32 + lane];
            u64 w0 = pack2(wv.x), w1 = pack2(wv.y);
            ulonglong2 p0 = zv[i * 3 + 0];
            ulonglong2 p1 = zv[i * 3 + 1];
            ulonglong2 p2 = zv[i * 3 + 2];
            ffma2(acc[0],  w0, p0.x); ffma2(acc[1],  w0, p0.y);
            ffma2(acc[2],  w0, p1.x); ffma2(acc[3],  w0, p1.y);
            ffma2(acc[4],  w0, p2.x); ffma2(acc[5],  w0, p2.y);
            ffma2(acc[6],  w1, p0.x); ffma2(acc[7],  w1, p0.y);
            ffma2(acc[8],  w1, p1.x); ffma2(acc[9],  w1, p1.y);
            ffma2(acc[10], w1, p2.x); ffma2(acc[11], w1, p2.y);
        }
        __syncwarp();   // all lanes done READING zA (aliased) before overwrite
#pragma unroll
        for (int p = 0; p < 6; p++) {
            float2 u = unpack2(acc[p]);
            z3t[(2 * p)     * 64 + lane] = fmaxf(u.x, 0.f);
            z3t[(2 * p + 1) * 64 + lane] = fmaxf(u.y, 0.f);
            float2 v = unpack2(acc[6 + p]);
            z3t[(2 * p)     * 64 + lane + 32] = fmaxf(v.x, 0.f);
            z3t[(2 * p + 1) * 64 + lane + 32] = fmaxf(v.y, 0.f);
        }
    }
    __syncwarp();

    // ---- layer 4: 64 -> 1 per L, mask, write ----
    if (lane < TOPK) {
        const float4* zv = reinterpret_cast<const float4*>(z3t) + lane * 16;
        const float4* wv = reinterpret_cast<const float4*>(W4);
        float a0 = b4[0], a1 = 0.f, a2 = 0.f, a3 = 0.f;
#pragma unroll
        for (int oc = 0; oc < 16; oc++) {
            float4 z = zv[oc];
            float4 ww = wv[oc];
            a0 = fmaf(ww.x, z.x, a0);
            a1 = fmaf(ww.y, z.y, a1);
            a2 = fmaf(ww.z, z.z, a2);
            a3 = fmaf(ww.w, z.w, a3);
        }
        float acc = (a0 + a1) + (a2 + a3);
        out[a * TOPK + lane] = acc * maskr;
        if (out_size >= 2 * N_AGENTS * TOPK)
            out[N_AGENTS * TOPK + a * TOPK + lane] = maskr;
    }
}

extern "C" void kernel_launch(void* const* d_in, const int* in_sizes, int n_in,
                              void* d_out, int out_size) {
    const float* states = (const float*)d_in[0];
    const float* W1 = (const float*)d_in[1];
    const float* b1 = (const float*)d_in[2];
    const float* W2 = (const float*)d_in[3];
    const float* b2 = (const float*)d_in[4];
    const float* W3 = (const float*)d_in[5];
    const float* b3 = (const float*)d_in[6];
    const float* W4 = (const float*)d_in[7];
    const float* b4 = (const float*)d_in[8];
    float* out = (float*)d_out;

    pack_kernel<<<16, 512>>>(states, W1, W2, W3);
    topk_kernel<<<TOPK_BLOCKS, 32 * TWPB>>>();
    mlp_kernel<<<N_AGENTS / 4, 128>>>((const float4*)states,
                                      b1, b2, b3, W4, b4, out, out_size);
}

// round 7
// speedup vs baseline: 1.2035x; 1.2035x over previous
#include <cuda_runtime.h>

typedef unsigned long long u64;

#define N_AGENTS 4096
#define TOPK 12
#define SEL 16
#define EPSC 1e-4f
#define TWPB 8                         // warps (rows) per topk block
#define BUFD 6
#define TOPK_BLOCKS (N_AGENTS / TWPB)  // 512

__device__ float2 g_W1p[6 * 32];        // [i][lane] -> W1 for outputs lane, lane+32
__device__ float4 g_W2p4[64 * 32];      // [i][lane] -> W2 for outputs lane+32q, q=0..3
__device__ float2 g_W3p[128 * 32];      // [i][lane] -> W3 for outputs lane, lane+32
__device__ float2 g_xy[N_AGENTS];       // packed (x,y)
__device__ int    g_idx[N_AGENTS * TOPK];
__device__ float  g_dn [N_AGENTS * TOPK];

static __device__ __forceinline__ u64 umin64(u64 a, u64 b) { return a < b ? a : b; }
static __device__ __forceinline__ u64 pack2(float w) {
    u64 r; asm("mov.b64 %0, {%1, %1};" : "=l"(r) : "f"(w)); return r;
}
static __device__ __forceinline__ void ffma2(u64 &d, u64 a, u64 b) {
    asm("fma.rn.f32x2 %0, %1, %2, %0;" : "+l"(d) : "l"(a), "l"(b));
}
static __device__ __forceinline__ float2 unpack2(u64 v) {
    return make_float2(__uint_as_float((unsigned)v), __uint_as_float((unsigned)(v >> 32)));
}

// ============================ pack kernel ============================
__global__ void pack_kernel(const float* __restrict__ states,
                            const float* __restrict__ W1,
                            const float* __restrict__ W2,
                            const float* __restrict__ W3)
{
    int t = blockIdx.x * blockDim.x + threadIdx.x;   // 0..4095
    if (t < 4096) {
        { // W3p: [i][lane]
            int i = t >> 5, lane = t & 31;
            g_W3p[t] = make_float2(W3[lane * 128 + i], W3[(lane + 32) * 128 + i]);
        }
        if (t < 2048) { // W2p4: [i][lane]
            int i = t >> 5, lane = t & 31;
            g_W2p4[t] = make_float4(W2[lane * 64 + i],        W2[(lane + 32) * 64 + i],
                                    W2[(lane + 64) * 64 + i], W2[(lane + 96) * 64 + i]);
        }
        if (t < 192) { // W1p
            int i = t >> 5, lane = t & 31;
            g_W1p[t] = make_float2(W1[lane * 6 + i], W1[(lane + 32) * 6 + i]);
        }
        g_xy[t] = make_float2(states[t * 4], states[t * 4 + 1]);
    }
}

// ============================ exact top-k ============================
static __device__ __forceinline__ void warp_merge(
    u64 &topent, u64 &thrkey, int &bcnt, u64 (*buf)[32], int lane)
{
    u64 v[BUFD];
#pragma unroll
    for (int s = 0; s < BUFD; s++) v[s] = (s < bcnt) ? buf[s][lane] : ~0ULL;
    u64 oldtop = topent;
    u64 newtop = ~0ULL;
#pragma unroll 1
    for (int r = 0; r < SEL; r++) {
        u64 lm = oldtop;
#pragma unroll
        for (int s = 0; s < BUFD; s++) lm = umin64(lm, v[s]);
#pragma unroll
        for (int o = 16; o > 0; o >>= 1)
            lm = umin64(lm, __shfl_xor_sync(0xffffffffu, lm, o));
        if (oldtop == lm) oldtop = ~0ULL;
#pragma unroll
        for (int s = 0; s < BUFD; s++) if (v[s] == lm) v[s] = ~0ULL;
        if (lane == r) newtop = lm;
        thrkey = lm;
    }
    topent = newtop;
    bcnt = 0;
}

__global__ __launch_bounds__(32 * TWPB) void topk_kernel()
{
    __shared__ u64 sbuf[TWPB][BUFD][32];

    const int warp = threadIdx.x >> 5;
    const int lane = threadIdx.x & 31;
    const int row  = blockIdx.x * TWPB + warp;
    const float2 sr = g_xy[row];
    const float xi = sr.x, yi = sr.y;
    const float4* xy4 = reinterpret_cast<const float4*>(g_xy);

    u64 topent = ~0ULL, thrkey = ~0ULL;
    int bcnt = 0;

    float4 p = xy4[lane];          // prefetch iter 0
#pragma unroll 1
    for (int m = 0; m < N_AGENTS / 64; m++) {
        float4 pn = xy4[(((m + 1) & 63) * 32) + lane];   // prefetch next (wraps)
        int j0 = m * 64 + 2 * lane;
        float dx0 = __fsub_rn(xi, p.x);
        float dy0 = __fsub_rn(yi, p.y);
        float d20 = __fadd_rn(__fadd_rn(__fmul_rn(dx0, dx0), EPSC),
                              __fadd_rn(__fmul_rn(dy0, dy0), EPSC));
        float dx1 = __fsub_rn(xi, p.z);
        float dy1 = __fsub_rn(yi, p.w);
        float d21 = __fadd_rn(__fadd_rn(__fmul_rn(dx1, dx1), EPSC),
                              __fadd_rn(__fmul_rn(dy1, dy1), EPSC));
        u64 key0 = ((u64)__float_as_uint(d20) << 32) | (unsigned)j0;
        u64 key1 = ((u64)__float_as_uint(d21) << 32) | (unsigned)(j0 + 1);
        if (key0 < thrkey) { sbuf[warp][bcnt][lane] = key0; bcnt++; }
        if (key1 < thrkey) { sbuf[warp][bcnt][lane] = key1; bcnt++; }
        if (__ballot_sync(0xffffffffu, bcnt > BUFD - 2))
            warp_merge(topent, thrkey, bcnt, sbuf[warp], lane);
        p = pn;
    }
    if (__ballot_sync(0xffffffffu, bcnt > 0))
        warp_merge(topent, thrkey, bcnt, sbuf[warp], lane);

    // re-rank survivors by (dn, idx) — JAX top_k tie semantics
    float d2v = __uint_as_float((unsigned)(topent >> 32));
    int   jv  = (int)(unsigned)(topent & 0xffffffffu);
    float dnv = __fsqrt_rn(d2v);
    int rank = 0;
#pragma unroll
    for (int ml = 0; ml < SEL; ml++) {
        float dm = __shfl_sync(0xffffffffu, dnv, ml);
        int   jm = __shfl_sync(0xffffffffu, jv,  ml);
        if (ml != lane && (dm < dnv || (dm == dnv && jm < jv))) rank++;
    }
    if (lane < SEL && rank < TOPK) {
        g_idx[row * TOPK + rank] = jv;
        g_dn [row * TOPK + rank] = dnv;
    }
}

// ============ MLP: half-agent per warp (6 columns), fully warp-private ============
// h0 column block [6h,6h+6) derives only from top-k positions {2c+h}; every layer
// preserves column privacy, so the two half-warps of an agent never communicate.
__global__ __launch_bounds__(128) void mlp_kernel(
    const float4* __restrict__ states,
    const float* __restrict__ b1, const float* __restrict__ b2,
    const float* __restrict__ b3,
    const float* __restrict__ W4, const float* __restrict__ b4,
    float* __restrict__ out, int out_size)
{
    __shared__ alignas(16) float smem[4][1600];
    const int t = threadIdx.x;
    const int w = t >> 5;
    const int lane = t & 31;
    const int g = blockIdx.x * 4 + w;
    const int a = g >> 1;          // agent
    const int h = g & 1;           // column half

    float* zB  = smem[w];          // [128][8] (6 used per row)
    float* zA  = smem[w] + 1024;   // [64][8]; later aliased as z3t [6][68]
    float* x6  = smem[w] + 1536;   // [6][8]
    float* z3t = zA;

    float maskr = 0.0f;
    if (lane < 6) {
        int l = 2 * lane + h;                  // interleaved top-k position
        int   idx = g_idx[a * TOPK + l];
        float dn  = g_dn [a * TOPK + l];
        float4 si = states[a];
        float4 sj = states[idx];
        x6[lane * 8 + 0] = __fsub_rn(si.x, sj.x);
        x6[lane * 8 + 1] = __fsub_rn(si.y, sj.y);
        x6[lane * 8 + 2] = __fsub_rn(si.z, sj.z);
        x6[lane * 8 + 3] = __fsub_rn(si.w, sj.w);
        x6[lane * 8 + 4] = (idx == a) ? 1.0f : 0.0f;
        x6[lane * 8 + 5] = __fsub_rn(dn, 0.8f);
        // mask for OUTPUT column 6h+lane (top-k position 6h+lane, unscrambled)
        maskr = (g_dn[a * TOPK + 6 * h + lane] <= 1.0f) ? 1.0f : 0.0f;
    }
    __syncwarp();

    // ---- layer 1: 6 -> 64, 2 outputs/lane, 3 f32x2 columns ----
    {
        u64 acc[6];
        u64 bb0 = pack2(b1[lane]), bb1 = pack2(b1[lane + 32]);
#pragma unroll
        for (int p = 0; p < 3; p++) { acc[p] = bb0; acc[3 + p] = bb1; }
        const u64* xu = reinterpret_cast<const u64*>(x6);
#pragma unroll
        for (int i = 0; i < 6; i++) {
            float2 wv = g_W1p[i * 32 + lane];
            u64 w0 = pack2(wv.x), w1 = pack2(wv.y);
            u64 a0 = xu[i * 4 + 0], a1 = xu[i * 4 + 1], a2 = xu[i * 4 + 2];
            ffma2(acc[0], w0, a0); ffma2(acc[1], w0, a1); ffma2(acc[2], w0, a2);
            ffma2(acc[3], w1, a0); ffma2(acc[4], w1, a1); ffma2(acc[5], w1, a2);
        }
        float2* zA2 = reinterpret_cast<float2*>(zA);
#pragma unroll
        for (int p = 0; p < 3; p++) {
            float2 u = unpack2(acc[p]);
            zA2[lane * 4 + p] = make_float2(fmaxf(u.x, 0.f), fmaxf(u.y, 0.f));
            float2 v = unpack2(acc[3 + p]);
            zA2[(lane + 32) * 4 + p] = make_float2(fmaxf(v.x, 0.f), fmaxf(v.y, 0.f));
        }
    }
    __syncwarp();

    // ---- layer 2: 64 -> 128, 4 outputs/lane, one pass ----
    {
        u64 acc[12];
#pragma unroll
        for (int q = 0; q < 4; q++) {
            u64 bb = pack2(b2[lane + 32 * q]);
#pragma unroll
            for (int p = 0; p < 3; p++) acc[q * 3 + p] = bb;
        }
#pragma unroll 2
        for (int i = 0; i < 64; i++) {
            float4 wv = g_W2p4[i * 32 + lane];
            u64 w0 = pack2(wv.x), w1 = pack2(wv.y), w2 = pack2(wv.z), w3 = pack2(wv.w);
            const u64* r = reinterpret_cast<const u64*>(zA + i * 8);
            u64 a0 = r[0], a1 = r[1], a2 = r[2];
            ffma2(acc[0],  w0, a0); ffma2(acc[1],  w0, a1); ffma2(acc[2],  w0, a2);
            ffma2(acc[3],  w1, a0); ffma2(acc[4],  w1, a1); ffma2(acc[5],  w1, a2);
            ffma2(acc[6],  w2, a0); ffma2(acc[7],  w2, a1); ffma2(acc[8],  w2, a2);
            ffma2(acc[9],  w3, a0); ffma2(acc[10], w3, a1); ffma2(acc[11], w3, a2);
        }
        float2* zB2 = reinterpret_cast<float2*>(zB);
#pragma unroll
        for (int q = 0; q < 4; q++) {
#pragma unroll
            for (int p = 0; p < 3; p++) {
                float2 u = unpack2(acc[q * 3 + p]);
                zB2[(lane + 32 * q) * 4 + p] =
                    make_float2(fmaxf(u.x, 0.f), fmaxf(u.y, 0.f));
            }
        }
    }
    __syncwarp();

    // ---- layer 3: 128 -> 64, 2 outputs/lane; store transposed z3t[6 c][68] ----
    {
        u64 acc[6];
        u64 bb0 = pack2(b3[lane]), bb1 = pack2(b3[lane + 32]);
#pragma unroll
        for (int p = 0; p < 3; p++) { acc[p] = bb0; acc[3 + p] = bb1; }
#pragma unroll 2
        for (int i = 0; i < 128; i++) {
            float2 wv = g_W3p[i * 32 + lane];
            u64 w0 = pack2(wv.x), w1 = pack2(wv.y);
            const u64* r = reinterpret_cast<const u64*>(zB + i * 8);
            u64 a0 = r[0], a1 = r[1], a2 = r[2];
            ffma2(acc[0], w0, a0); ffma2(acc[1], w0, a1); ffma2(acc[2], w0, a2);
            ffma2(acc[3], w1, a0); ffma2(acc[4], w1, a1); ffma2(acc[5], w1, a2);
        }
        __syncwarp();   // (zA alias) — all L2 reads of zA precede these stores
#pragma unroll
        for (int p = 0; p < 3; p++) {
            float2 u = unpack2(acc[p]);
            z3t[(2 * p)     * 68 + lane] = fmaxf(u.x, 0.f);
            z3t[(2 * p + 1) * 68 + lane] = fmaxf(u.y, 0.f);
            float2 v = unpack2(acc[3 + p]);
            z3t[(2 * p)     * 68 + lane + 32] = fmaxf(v.x, 0.f);
            z3t[(2 * p + 1) * 68 + lane + 32] = fmaxf(v.y, 0.f);
        }
    }
    __syncwarp();

    // ---- layer 4: 64 -> 1 per column, mask, write ----
    if (lane < 6) {
        const float4* zv = reinterpret_cast<const float4*>(z3t + lane * 68);
        const float4* wv = reinterpret_cast<const float4*>(W4);
        float a0 = b4[0], a1 = 0.f, a2 = 0.f, a3 = 0.f;
#pragma unroll
        for (int oc = 0; oc < 16; oc++) {
            float4 z = zv[oc];
            float4 ww = wv[oc];
            a0 = fmaf(ww.x, z.x, a0);
            a1 = fmaf(ww.y, z.y, a1);
            a2 = fmaf(ww.z, z.z, a2);
            a3 = fmaf(ww.w, z.w, a3);
        }
        float acc = (a0 + a1) + (a2 + a3);
        int oidx = a * TOPK + 6 * h + lane;
        out[oidx] = acc * maskr;
        if (out_size >= 2 * N_AGENTS * TOPK)
            out[N_AGENTS * TOPK + oidx] = maskr;
    }
}

extern "C" void kernel_launch(void* const* d_in, const int* in_sizes, int n_in,
                              void* d_out, int out_size) {
    const float* states = (const float*)d_in[0];
    const float* W1 = (const float*)d_in[1];
    const float* b1 = (const float*)d_in[2];
    const float* W2 = (const float*)d_in[3];
    const float* b2 = (const float*)d_in[4];
    const float* W3 = (const float*)d_in[5];
    const float* b3 = (const float*)d_in[6];
    const float* W4 = (const float*)d_in[7];
    const float* b4 = (const float*)d_in[8];
    float* out = (float*)d_out;

    pack_kernel<<<8, 512>>>(states, W1, W2, W3);
    topk_kernel<<<TOPK_BLOCKS, 32 * TWPB>>>();
    // 8192 half-agent warps, 4 per CTA
    mlp_kernel<<<N_AGENTS * 2 / 4, 128>>>((const float4*)states,
                                          b1, b2, b3, W4, b4, out, out_size);
}